// round 15
// baseline (speedup 1.0000x reference)
#include <cuda_runtime.h>
#include <math.h>

#define NN 50000
#define NR 500
#define E1C 200000
#define E2C 50000
#define EC 250000

// ---------------- scratch (device globals; no allocation allowed) ----------
__device__ float g_PQ1[(size_t)NN * 512];      // [n][h*256 + {P:0..127, Q:128..255}]
__device__ float g_s1[4 * NN];                 // p_h0,p_h1,q_h0,q_h1
__device__ float g_relA3[2 * NR * 128];
__device__ float g_rs1[2 * NR];
__device__ float g_out1[(size_t)NN * 256];
__device__ float g_C2[(size_t)NN * 768];       // X1|X2|X3
__device__ float g_s2[3 * NN];                 // p1,q2,q3(=p3)
__device__ float g_W3rel[NR * 256];
__device__ float g_rs2[NR];
__device__ float g_Wc1[128 * 512];             // B1 [K=128][N=512]
__device__ float g_B2[256 * 768];              // B2 [K=256][N=768]
__device__ float g_v1[2 * 128];
__device__ float g_v2[2 * 128];
__device__ float g_u[3 * 256];
// CSR over src (same src array for both layers) + packed per-edge info
__device__ int g_deg[NN];
__device__ int g_cur[NN];
__device__ int g_rowstart[NN + 1];
__device__ int4 g_einfo[EC];                   // {dst, r0, r1(-1 if direct), pad}

// ---------------- packed f32x2 helpers (Blackwell; NOT mma) -----------------
#define FFMA2(d, a, b)                                                      \
    asm("fma.rn.f32x2 %0, %1, %2, %0;" : "+l"(d) : "l"(a), "l"(b))
#define PACK_DUP(d, x)                                                      \
    asm("mov.b64 %0, {%1, %1};" : "=l"(d) : "r"(__float_as_uint(x)))

__device__ __forceinline__ float ull_lo(unsigned long long u) {
    return __uint_as_float((unsigned)(u & 0xffffffffu));
}
__device__ __forceinline__ float ull_hi(unsigned long long u) {
    return __uint_as_float((unsigned)(u >> 32));
}
__device__ __forceinline__ float elu1(float v) {
    return v > 0.f ? v : expm1f(v);
}

// ---------------- CSR build -------------------------------------------------
__global__ void zero_small() {
    int i = blockIdx.x * 256 + threadIdx.x;
    if (i < NN) { g_deg[i] = 0; g_cur[i] = 0; }
}

__global__ void hist(const int* __restrict__ el1, const int* __restrict__ el2) {
    int e = blockIdx.x * 256 + threadIdx.x;
    if (e >= EC) return;
    int src = (e < E1C) ? el1[e] : el2[e - E1C];
    atomicAdd(&g_deg[src], 1);
}

__global__ void scan_deg() {
    __shared__ int sm[1024];
    __shared__ int s_carry;
    int t = threadIdx.x;
    if (t == 0) s_carry = 0;
    __syncthreads();
    const int NCH = (NN + 1023) / 1024;
    for (int ch = 0; ch < NCH; ch++) {
        int i = ch * 1024 + t;
        int v = (i < NN) ? g_deg[i] : 0;
        sm[t] = v;
        __syncthreads();
        for (int off = 1; off < 1024; off <<= 1) {
            int x = (t >= off) ? sm[t - off] : 0;
            __syncthreads();
            sm[t] += x;
            __syncthreads();
        }
        int c = s_carry;
        if (i < NN) g_rowstart[i] = c + sm[t] - v;   // exclusive
        __syncthreads();
        if (t == 0) s_carry = c + sm[1023];
        __syncthreads();
    }
    if (t == 0) g_rowstart[NN] = s_carry;
}

// scatter + einfo build: decode each edge once, store packed {dst, r0, r1}
__global__ void scatter(const int* __restrict__ el1, const int* __restrict__ rt1,
                        const int* __restrict__ el2, const int* __restrict__ rt2) {
    int e = blockIdx.x * 256 + threadIdx.x;
    if (e >= EC) return;
    int src, dst, r0, r1;
    if (e < E1C) {
        src = el1[e]; dst = el1[E1C + e];
        r0 = rt1[e]; r1 = -1;
    } else {
        int en = e - E1C;
        src = el2[en]; dst = el2[E2C + en];
        r0 = rt2[2 * en]; r1 = rt2[2 * en + 1];
    }
    int slot = g_rowstart[src] + atomicAdd(&g_cur[src], 1);
    g_einfo[slot] = make_int4(dst, r0, r1, 0);
}

// ---------------- small weight preps --------------------------------------
__global__ void prep_wc1(const float* __restrict__ aH) {
    int idx = blockIdx.x * blockDim.x + threadIdx.x;
    if (idx >= 128 * 512) return;
    int k = idx >> 9, col = idx & 511;
    int h = col >> 8, c = col & 255;
    const float* row = aH + ((size_t)h * 128 + (c & 127)) * 384;
    float v = (c < 128) ? (row[k] + row[256 + k]) : (row[128 + k] + row[256 + k]);
    g_Wc1[idx] = v;
}

__global__ void prep_v(const float* __restrict__ aH, const float* __restrict__ a2H) {
    int h = blockIdx.x, k = threadIdx.x;
    float s1 = 0.f, s2 = 0.f;
    for (int j = 0; j < 128; j++) {
        float a2 = a2H[h * 128 + j];
        const float* row = aH + ((size_t)h * 128 + j) * 384;
        s1 += a2 * (row[k] + row[256 + k]);
        s2 += a2 * (row[128 + k] + row[256 + k]);
    }
    g_v1[h * 128 + k] = s1;
    g_v2[h * 128 + k] = s2;
}

__global__ void prep_b2(const float* __restrict__ aO) {
    int idx = blockIdx.x * blockDim.x + threadIdx.x;
    if (idx >= 256 * 768) return;
    int k = idx / 768, m = idx % 768;
    g_B2[idx] = aO[(size_t)(m & 255) * 768 + (m >> 8) * 256 + k];
}

__global__ void prep_u(const float* __restrict__ aO, const float* __restrict__ a2O) {
    int b = blockIdx.x, k = threadIdx.x;
    float s = 0.f;
    for (int j = 0; j < 256; j++) s += a2O[j] * aO[(size_t)j * 768 + b * 256 + k];
    g_u[b * 256 + k] = s;
}

__global__ void rel_transform1(const float* __restrict__ rel,
                               const float* __restrict__ aH,
                               const float* __restrict__ a2H) {
    int r = blockIdx.x, h = blockIdx.y, j = threadIdx.x;
    __shared__ float rrow[128];
    __shared__ float sred[128];
    rrow[j] = rel[(size_t)r * 128 + j];
    __syncthreads();
    const float* arow = aH + ((size_t)h * 128 + j) * 384 + 256;
    float s = 0.f;
#pragma unroll 8
    for (int t = 0; t < 128; t++) s += rrow[t] * arow[t];
    g_relA3[((size_t)h * NR + r) * 128 + j] = s;
    sred[j] = s * a2H[h * 128 + j];
    __syncthreads();
    for (int o = 64; o; o >>= 1) { if (j < o) sred[j] += sred[j + o]; __syncthreads(); }
    if (j == 0) g_rs1[h * NR + r] = sred[0];
}

__global__ void rel_transform2(const float* __restrict__ rel,
                               const float* __restrict__ W,
                               const float* __restrict__ aO,
                               const float* __restrict__ a2O,
                               float* __restrict__ out_rel_dst) {
    int r = blockIdx.x, j = threadIdx.x; // 256 threads
    __shared__ float rrow[128];
    __shared__ float orow[256];
    __shared__ float sred[256];
    if (j < 128) rrow[j] = rel[(size_t)r * 128 + j];
    __syncthreads();
    float o = 0.f;
#pragma unroll 8
    for (int t = 0; t < 128; t++) o += rrow[t] * W[(size_t)t * 256 + j];
    orow[j] = o;
    out_rel_dst[(size_t)r * 256 + j] = o;
    __syncthreads();
    const float* arow = aO + (size_t)j * 768 + 512;
    float w3 = 0.f;
#pragma unroll 8
    for (int m = 0; m < 256; m++) w3 += orow[m] * arow[m];
    g_W3rel[(size_t)r * 256 + j] = w3;
    sred[j] = w3 * a2O[j];
    __syncthreads();
    for (int o2 = 128; o2; o2 >>= 1) { if (j < o2) sred[j] += sred[j + o2]; __syncthreads(); }
    if (j == 0) g_rs2[r] = sred[0];
}

// ---------------- SGEMM (128x128 tile, BK=16, double-buffered, f32x2) ------
// Warp shape 4 ty x 8 tx (warp tile 32 rows x 64 cols): per-kk smem
// wavefronts drop from 10 to 6 (A: 2x1, B: 2x2) vs the old 2x16 shape.
__device__ __forceinline__ void sgemm_body(const float* __restrict__ A,
                                           const float* __restrict__ B,
                                           float* __restrict__ C,
                                           int M, int N, int K) {
    __shared__ float As[2][16][128];
    __shared__ float Bs[2][16][128];
    const int m0 = blockIdx.y * 128;
    const int n0 = blockIdx.x * 128;
    const int t = threadIdx.x;
    const int aRow0 = t >> 2;
    const int aRow1 = aRow0 + 64;
    const int aC = (t & 3) * 4;
    const int bRow0 = t >> 5;
    const int bRow1 = bRow0 + 8;
    const int bC = (t & 31) * 4;
    // warp tile 32x64
    const int warp = t >> 5, lane = t & 31;
    const int ty = (warp >> 1) * 4 + (lane >> 3);
    const int tx = (warp & 1) * 8 + (lane & 7);

    int ar0 = m0 + aRow0; if (ar0 >= M) ar0 = M - 1;
    int ar1 = m0 + aRow1; if (ar1 >= M) ar1 = M - 1;

    unsigned long long acc[8][4];
#pragma unroll
    for (int i = 0; i < 8; i++)
#pragma unroll
        for (int j = 0; j < 4; j++) acc[i][j] = 0ull;

    float4 fa0 = *(const float4*)(A + (size_t)ar0 * K + aC);
    float4 fa1 = *(const float4*)(A + (size_t)ar1 * K + aC);
    float4 fb0 = *(const float4*)(B + (size_t)bRow0 * N + n0 + bC);
    float4 fb1 = *(const float4*)(B + (size_t)bRow1 * N + n0 + bC);
    As[0][aC + 0][aRow0] = fa0.x; As[0][aC + 1][aRow0] = fa0.y;
    As[0][aC + 2][aRow0] = fa0.z; As[0][aC + 3][aRow0] = fa0.w;
    As[0][aC + 0][aRow1] = fa1.x; As[0][aC + 1][aRow1] = fa1.y;
    As[0][aC + 2][aRow1] = fa1.z; As[0][aC + 3][aRow1] = fa1.w;
    *(float4*)&Bs[0][bRow0][bC] = fb0;
    *(float4*)&Bs[0][bRow1][bC] = fb1;
    __syncthreads();

    const int NK = K >> 4;
    for (int kt = 0; kt < NK; kt++) {
        const int cur = kt & 1;
        const int nxt = cur ^ 1;
        const bool more = (kt + 1 < NK);
        if (more) {
            int kc = (kt + 1) * 16;
            fa0 = *(const float4*)(A + (size_t)ar0 * K + kc + aC);
            fa1 = *(const float4*)(A + (size_t)ar1 * K + kc + aC);
            fb0 = *(const float4*)(B + (size_t)(kc + bRow0) * N + n0 + bC);
            fb1 = *(const float4*)(B + (size_t)(kc + bRow1) * N + n0 + bC);
        }
#pragma unroll
        for (int kk = 0; kk < 16; kk++) {
            float ar[8];
            *(float4*)(ar)     = *(const float4*)&As[cur][kk][ty * 8];
            *(float4*)(ar + 4) = *(const float4*)&As[cur][kk][ty * 8 + 4];
            unsigned long long bp[4];
            *(ulonglong2*)(bp)     = *(const ulonglong2*)&Bs[cur][kk][tx * 8];
            *(ulonglong2*)(bp + 2) = *(const ulonglong2*)&Bs[cur][kk][tx * 8 + 4];
#pragma unroll
            for (int i = 0; i < 8; i++) {
                unsigned long long ap;
                PACK_DUP(ap, ar[i]);
                FFMA2(acc[i][0], ap, bp[0]);
                FFMA2(acc[i][1], ap, bp[1]);
                FFMA2(acc[i][2], ap, bp[2]);
                FFMA2(acc[i][3], ap, bp[3]);
            }
        }
        if (more) {
            As[nxt][aC + 0][aRow0] = fa0.x; As[nxt][aC + 1][aRow0] = fa0.y;
            As[nxt][aC + 2][aRow0] = fa0.z; As[nxt][aC + 3][aRow0] = fa0.w;
            As[nxt][aC + 0][aRow1] = fa1.x; As[nxt][aC + 1][aRow1] = fa1.y;
            As[nxt][aC + 2][aRow1] = fa1.z; As[nxt][aC + 3][aRow1] = fa1.w;
            *(float4*)&Bs[nxt][bRow0][bC] = fb0;
            *(float4*)&Bs[nxt][bRow1][bC] = fb1;
        }
        __syncthreads();
    }

#pragma unroll
    for (int i = 0; i < 8; i++) {
        int row = m0 + ty * 8 + i;
        if (row < M) {
            float* cp = C + (size_t)row * N + n0 + tx * 8;
            *(float4*)cp = make_float4(ull_lo(acc[i][0]), ull_hi(acc[i][0]),
                                       ull_lo(acc[i][1]), ull_hi(acc[i][1]));
            *(float4*)(cp + 4) = make_float4(ull_lo(acc[i][2]), ull_hi(acc[i][2]),
                                             ull_lo(acc[i][3]), ull_hi(acc[i][3]));
        }
    }
}

__global__ void __launch_bounds__(256) sgemm_l1(const float* __restrict__ ent) {
    sgemm_body(ent, g_Wc1, g_PQ1, NN, 512, 128);
}
__global__ void __launch_bounds__(256) sgemm_l2() {
    sgemm_body(g_out1, g_B2, g_C2, NN, 768, 256);
}

// ---------------- per-node attention scalars -------------------------------
__global__ void node_scalars1(const float* __restrict__ ent) {
    int gw = (blockIdx.x * blockDim.x + threadIdx.x) >> 5;
    int lane = threadIdx.x & 31;
    if (gw >= NN) return;
    float4 x = *(const float4*)(ent + (size_t)gw * 128 + lane * 4);
    float r[4];
#pragma unroll
    for (int h = 0; h < 2; h++) {
        float4 v = *(const float4*)(g_v1 + h * 128 + lane * 4);
        r[h] = x.x * v.x + x.y * v.y + x.z * v.z + x.w * v.w;
        float4 u = *(const float4*)(g_v2 + h * 128 + lane * 4);
        r[2 + h] = x.x * u.x + x.y * u.y + x.z * u.z + x.w * u.w;
    }
#pragma unroll
    for (int b = 0; b < 4; b++)
        for (int o = 16; o; o >>= 1) r[b] += __shfl_xor_sync(0xffffffffu, r[b], o);
    if (lane == 0) {
        g_s1[0 * NN + gw] = r[0];
        g_s1[1 * NN + gw] = r[1];
        g_s1[2 * NN + gw] = r[2];
        g_s1[3 * NN + gw] = r[3];
    }
}

__global__ void node_scalars2() {
    int gw = (blockIdx.x * blockDim.x + threadIdx.x) >> 5;
    int lane = threadIdx.x & 31;
    if (gw >= NN) return;
    const float* row = g_out1 + (size_t)gw * 256;
    float4 x0 = *(const float4*)(row + lane * 4);
    float4 x1 = *(const float4*)(row + 128 + lane * 4);
    float r[3];
#pragma unroll
    for (int b = 0; b < 3; b++) {
        const float* u = g_u + b * 256;
        float4 u0 = *(const float4*)(u + lane * 4);
        float4 u1 = *(const float4*)(u + 128 + lane * 4);
        r[b] = x0.x * u0.x + x0.y * u0.y + x0.z * u0.z + x0.w * u0.w
             + x1.x * u1.x + x1.y * u1.y + x1.z * u1.z + x1.w * u1.w;
    }
#pragma unroll
    for (int b = 0; b < 3; b++)
        for (int o = 16; o; o >>= 1) r[b] += __shfl_xor_sync(0xffffffffu, r[b], o);
    if (lane == 0) {
        g_s2[gw] = r[0];
        g_s2[NN + gw] = r[1];
        g_s2[2 * NN + gw] = r[2];
    }
}

// ---------------- CSR edge passes: warp/node, chunked einfo + shfl ---------
__global__ void edge_pass1_csr() {
    int n = (blockIdx.x * blockDim.x + threadIdx.x) >> 5;
    int lane = threadIdx.x & 31;
    if (n >= NN) return;
    const int beg = g_rowstart[n], end = g_rowstart[n + 1];
    const int j = lane * 4;
    const float sn0 = g_s1[n];
    const float sn1 = g_s1[NN + n];
    float4 a0 = make_float4(0.f, 0.f, 0.f, 0.f);
    float4 a1 = make_float4(0.f, 0.f, 0.f, 0.f);
    float rs0 = 0.f, rs1 = 0.f;

    for (int pos = beg; pos < end; pos += 32) {
        int m = end - pos; if (m > 32) m = 32;
        int4 info = make_int4(0, 0, -1, 0);
        if (lane < m) info = g_einfo[pos + lane];   // one coalesced load / chunk
        for (int k = 0; k < m; k++) {
            int dst = __shfl_sync(0xffffffffu, info.x, k);
            int r0i = __shfl_sync(0xffffffffu, info.y, k);
            int r1i = __shfl_sync(0xffffffffu, info.z, k);
            // head 0
            {
                float s = sn0 + g_s1[2 * NN + dst] + g_rs1[r0i];
                float4 r = *(const float4*)(g_relA3 + (size_t)r0i * 128 + j);
                float4 q = *(const float4*)(g_PQ1 + (size_t)dst * 512 + 128 + j);
                float vx = q.x + r.x, vy = q.y + r.y, vz = q.z + r.z, vw = q.w + r.w;
                if (r1i >= 0) {
                    s += g_rs1[r1i];
                    float4 r2 = *(const float4*)(g_relA3 + (size_t)r1i * 128 + j);
                    vx += r2.x; vy += r2.y; vz += r2.z; vw += r2.w;
                }
                float w = expf(-(s > 0.f ? s : 0.2f * s));
                rs0 += w;
                a0.x += w * vx; a0.y += w * vy; a0.z += w * vz; a0.w += w * vw;
            }
            // head 1
            {
                float s = sn1 + g_s1[3 * NN + dst] + g_rs1[NR + r0i];
                float4 r = *(const float4*)(g_relA3 + (size_t)(NR + r0i) * 128 + j);
                float4 q = *(const float4*)(g_PQ1 + (size_t)dst * 512 + 384 + j);
                float vx = q.x + r.x, vy = q.y + r.y, vz = q.z + r.z, vw = q.w + r.w;
                if (r1i >= 0) {
                    s += g_rs1[NR + r1i];
                    float4 r2 = *(const float4*)(g_relA3 + (size_t)(NR + r1i) * 128 + j);
                    vx += r2.x; vy += r2.y; vz += r2.z; vw += r2.w;
                }
                float w = expf(-(s > 0.f ? s : 0.2f * s));
                rs1 += w;
                a1.x += w * vx; a1.y += w * vy; a1.z += w * vz; a1.w += w * vw;
            }
        }
    }

    float4 o0 = make_float4(0.f, 0.f, 0.f, 0.f);
    float4 o1 = make_float4(0.f, 0.f, 0.f, 0.f);
    if (end > beg) {
        float4 p0 = *(const float4*)(g_PQ1 + (size_t)n * 512 + j);
        float4 p1 = *(const float4*)(g_PQ1 + (size_t)n * 512 + 256 + j);
        float i0 = 1.f / rs0, i1 = 1.f / rs1;
        o0.x = elu1(p0.x + a0.x * i0); o0.y = elu1(p0.y + a0.y * i0);
        o0.z = elu1(p0.z + a0.z * i0); o0.w = elu1(p0.w + a0.w * i0);
        o1.x = elu1(p1.x + a1.x * i1); o1.y = elu1(p1.y + a1.y * i1);
        o1.z = elu1(p1.z + a1.z * i1); o1.w = elu1(p1.w + a1.w * i1);
    }
    *(float4*)(g_out1 + (size_t)n * 256 + j) = o0;
    *(float4*)(g_out1 + (size_t)n * 256 + 128 + j) = o1;
}

__global__ void edge_pass2_csr(float* __restrict__ out) {
    int n = (blockIdx.x * blockDim.x + threadIdx.x) >> 5;
    int lane = threadIdx.x & 31;
    if (n >= NN) return;
    const int beg = g_rowstart[n], end = g_rowstart[n + 1];
    const int j = lane * 4;
    const float sn = g_s2[n];
    const float sn3 = g_s2[2 * NN + n];
    float4 alo = make_float4(0.f, 0.f, 0.f, 0.f);
    float4 ahi = make_float4(0.f, 0.f, 0.f, 0.f);
    float rs = 0.f, rsN = 0.f;

    for (int pos = beg; pos < end; pos += 32) {
        int m = end - pos; if (m > 32) m = 32;
        int4 info = make_int4(0, 0, -1, 0);
        if (lane < m) info = g_einfo[pos + lane];
        for (int k = 0; k < m; k++) {
            int dst = __shfl_sync(0xffffffffu, info.x, k);
            int r0i = __shfl_sync(0xffffffffu, info.y, k);
            int r1i = __shfl_sync(0xffffffffu, info.z, k);
            float s = sn + g_s2[NN + dst] + g_rs2[r0i];
            const float* c2d = g_C2 + (size_t)dst * 768;
            const float* w0 = g_W3rel + (size_t)r0i * 256;
            float4 xlo = *(const float4*)(c2d + 256 + j);
            float4 xhi = *(const float4*)(c2d + 384 + j);
            float4 vlo = *(const float4*)(w0 + j);
            float4 vhi = *(const float4*)(w0 + 128 + j);
            float lx = xlo.x + vlo.x, ly = xlo.y + vlo.y;
            float lz = xlo.z + vlo.z, lw = xlo.w + vlo.w;
            float hx = xhi.x + vhi.x, hy = xhi.y + vhi.y;
            float hz = xhi.z + vhi.z, hw = xhi.w + vhi.w;
            if (r1i >= 0) {
                s += sn3 + g_s2[2 * NN + dst] + g_rs2[r1i];
                const float* w1 = g_W3rel + (size_t)r1i * 256;
                float4 x3lo = *(const float4*)(c2d + 512 + j);
                float4 x3hi = *(const float4*)(c2d + 640 + j);
                float4 ulo = *(const float4*)(w1 + j);
                float4 uhi = *(const float4*)(w1 + 128 + j);
                lx += x3lo.x + ulo.x; ly += x3lo.y + ulo.y;
                lz += x3lo.z + ulo.z; lw += x3lo.w + ulo.w;
                hx += x3hi.x + uhi.x; hy += x3hi.y + uhi.y;
                hz += x3hi.z + uhi.z; hw += x3hi.w + uhi.w;
            }
            float w = expf(-(s > 0.f ? s : 0.2f * s));
            rs += w;
            if (r1i >= 0) rsN += w;
            alo.x += w * lx; alo.y += w * ly; alo.z += w * lz; alo.w += w * lw;
            ahi.x += w * hx; ahi.y += w * hy; ahi.z += w * hz; ahi.w += w * hw;
        }
    }

    float4 olo = make_float4(0.f, 0.f, 0.f, 0.f);
    float4 ohi = make_float4(0.f, 0.f, 0.f, 0.f);
    if (end > beg) {
        const float* c2n = g_C2 + (size_t)n * 768;
        float4 x1lo = *(const float4*)(c2n + j);
        float4 x1hi = *(const float4*)(c2n + 128 + j);
        float4 x3lo = *(const float4*)(c2n + 512 + j);
        float4 x3hi = *(const float4*)(c2n + 640 + j);
        float inv = 1.f / rs;
        olo.x = elu1(x1lo.x + (rsN * x3lo.x + alo.x) * inv);
        olo.y = elu1(x1lo.y + (rsN * x3lo.y + alo.y) * inv);
        olo.z = elu1(x1lo.z + (rsN * x3lo.z + alo.z) * inv);
        olo.w = elu1(x1lo.w + (rsN * x3lo.w + alo.w) * inv);
        ohi.x = elu1(x1hi.x + (rsN * x3hi.x + ahi.x) * inv);
        ohi.y = elu1(x1hi.y + (rsN * x3hi.y + ahi.y) * inv);
        ohi.z = elu1(x1hi.z + (rsN * x3hi.z + ahi.z) * inv);
        ohi.w = elu1(x1hi.w + (rsN * x3hi.w + ahi.w) * inv);
    }
    *(float4*)(out + (size_t)n * 256 + j) = olo;
    *(float4*)(out + (size_t)n * 256 + 128 + j) = ohi;
}

// ---------------- launch ----------------------------------------------------
extern "C" void kernel_launch(void* const* d_in, const int* in_sizes, int n_in,
                              void* d_out, int out_size) {
    const float* ent = (const float*)d_in[0];   // [50000,128]
    const float* rel = (const float*)d_in[1];   // [500,128]
    const int*   el1 = (const int*)d_in[2];     // [2,200000]
    const int*   rt1 = (const int*)d_in[3];     // [200000]
    const int*   el2 = (const int*)d_in[4];     // [2,50000]
    const int*   rt2 = (const int*)d_in[5];     // [50000,2]
    const float* aH  = (const float*)d_in[6];   // [2,128,384]
    const float* a2H = (const float*)d_in[7];   // [2,128]
    const float* W   = (const float*)d_in[8];   // [128,256]
    const float* aO  = (const float*)d_in[9];   // [256,768]
    const float* a2O = (const float*)d_in[10];  // [256]
    float* out = (float*)d_out;                 // out_ent [50000,256] ++ out_rel [500,256]

    // place sgemm_l1 as 4th launch (ncu sampling lands there) with deps satisfied
    zero_small<<<(NN + 255) / 256, 256>>>();
    prep_wc1<<<256, 256>>>(aH);
    hist<<<(EC + 255) / 256, 256>>>(el1, el2);
    sgemm_l1<<<dim3(4, 391), 256>>>(ent);
    scan_deg<<<1, 1024>>>();
    scatter<<<(EC + 255) / 256, 256>>>(el1, rt1, el2, rt2);
    prep_v<<<2, 128>>>(aH, a2H);
    node_scalars1<<<(NN * 32 + 255) / 256, 256>>>(ent);
    rel_transform1<<<dim3(NR, 2), 128>>>(rel, aH, a2H);
    edge_pass1_csr<<<(NN * 32 + 255) / 256, 256>>>();

    prep_b2<<<768, 256>>>(aO);
    prep_u<<<3, 256>>>(aO, a2O);
    rel_transform2<<<NR, 256>>>(rel, W, aO, a2O, out + (size_t)NN * 256);
    sgemm_l2<<<dim3(6, 391), 256>>>();
    node_scalars2<<<(NN * 32 + 255) / 256, 256>>>();
    edge_pass2_csr<<<(NN * 32 + 255) / 256, 256>>>(out);
}

// round 16
// speedup vs baseline: 1.0351x; 1.0351x over previous
#include <cuda_runtime.h>
#include <math.h>

#define NN 50000
#define NR 500
#define E1C 200000
#define E2C 50000
#define EC 250000

// ---------------- scratch (device globals; no allocation allowed) ----------
__device__ float g_PQ1[(size_t)NN * 512];      // [n][h*256 + {P:0..127, Q:128..255}]
__device__ float g_s1[4 * NN];                 // p_h0,p_h1,q_h0,q_h1
__device__ float g_relA3[2 * NR * 128];
__device__ float g_rs1[2 * NR];
__device__ float g_out1[(size_t)NN * 256];
__device__ float g_C2[(size_t)NN * 768];       // X1|X2|X3
__device__ float g_s2[3 * NN];                 // p1,q2,q3(=p3)
__device__ float g_W3rel[NR * 256];
__device__ float g_rs2[NR];
__device__ float g_Wc1[128 * 512];             // B1 [K=128][N=512]
__device__ float g_B2[256 * 768];              // B2 [K=256][N=768]
__device__ float g_v1[2 * 128];
__device__ float g_v2[2 * 128];
__device__ float g_u[3 * 256];
// CSR over src (same src array for both layers) + packed per-edge info
__device__ int g_deg[NN];
__device__ int g_cur[NN];
__device__ int g_rowstart[NN + 1];
__device__ int4 g_einfo[EC];                   // {dst, r0, r1(-1 if direct), pad}

// ---------------- packed f32x2 helpers (Blackwell; NOT mma) -----------------
#define FFMA2(d, a, b)                                                      \
    asm("fma.rn.f32x2 %0, %1, %2, %0;" : "+l"(d) : "l"(a), "l"(b))
#define PACK_DUP(d, x)                                                      \
    asm("mov.b64 %0, {%1, %1};" : "=l"(d) : "r"(__float_as_uint(x)))

__device__ __forceinline__ float ull_lo(unsigned long long u) {
    return __uint_as_float((unsigned)(u & 0xffffffffu));
}
__device__ __forceinline__ float ull_hi(unsigned long long u) {
    return __uint_as_float((unsigned)(u >> 32));
}
__device__ __forceinline__ float elu1(float v) {
    return v > 0.f ? v : expm1f(v);
}

// ---------------- CSR build -------------------------------------------------
__global__ void zero_small() {
    int i = blockIdx.x * 256 + threadIdx.x;
    if (i < NN) { g_deg[i] = 0; g_cur[i] = 0; }
}

__global__ void hist(const int* __restrict__ el1, const int* __restrict__ el2) {
    int e = blockIdx.x * 256 + threadIdx.x;
    if (e >= EC) return;
    int src = (e < E1C) ? el1[e] : el2[e - E1C];
    atomicAdd(&g_deg[src], 1);
}

// shuffle-based scan: 4 barriers/chunk instead of 21
__global__ void scan_deg() {
    __shared__ int wsum[32];
    __shared__ int s_carry;
    int t = threadIdx.x;
    int lane = t & 31, wid = t >> 5;
    if (t == 0) s_carry = 0;
    __syncthreads();
    const int NCH = (NN + 1023) / 1024;
    for (int ch = 0; ch < NCH; ch++) {
        int i = ch * 1024 + t;
        int v = (i < NN) ? g_deg[i] : 0;
        int x = v;
#pragma unroll
        for (int o = 1; o < 32; o <<= 1) {
            int y = __shfl_up_sync(0xffffffffu, x, o);
            if (lane >= o) x += y;
        }
        if (lane == 31) wsum[wid] = x;
        __syncthreads();
        if (wid == 0) {
            int s = wsum[lane];
#pragma unroll
            for (int o = 1; o < 32; o <<= 1) {
                int y = __shfl_up_sync(0xffffffffu, s, o);
                if (lane >= o) s += y;
            }
            wsum[lane] = s;
        }
        __syncthreads();
        int base = s_carry + (wid > 0 ? wsum[wid - 1] : 0);
        if (i < NN) g_rowstart[i] = base + x - v;   // exclusive
        __syncthreads();
        if (t == 0) s_carry += wsum[31];
        __syncthreads();
    }
    if (t == 0) g_rowstart[NN] = s_carry;
}

// scatter + einfo build: decode each edge once, store packed {dst, r0, r1}
__global__ void scatter(const int* __restrict__ el1, const int* __restrict__ rt1,
                        const int* __restrict__ el2, const int* __restrict__ rt2) {
    int e = blockIdx.x * 256 + threadIdx.x;
    if (e >= EC) return;
    int src, dst, r0, r1;
    if (e < E1C) {
        src = el1[e]; dst = el1[E1C + e];
        r0 = rt1[e]; r1 = -1;
    } else {
        int en = e - E1C;
        src = el2[en]; dst = el2[E2C + en];
        r0 = rt2[2 * en]; r1 = rt2[2 * en + 1];
    }
    int slot = g_rowstart[src] + atomicAdd(&g_cur[src], 1);
    g_einfo[slot] = make_int4(dst, r0, r1, 0);
}

// ---------------- small weight preps --------------------------------------
__global__ void prep_wc1(const float* __restrict__ aH) {
    int idx = blockIdx.x * blockDim.x + threadIdx.x;
    if (idx >= 128 * 512) return;
    int k = idx >> 9, col = idx & 511;
    int h = col >> 8, c = col & 255;
    const float* row = aH + ((size_t)h * 128 + (c & 127)) * 384;
    float v = (c < 128) ? (row[k] + row[256 + k]) : (row[128 + k] + row[256 + k]);
    g_Wc1[idx] = v;
}

__global__ void prep_v(const float* __restrict__ aH, const float* __restrict__ a2H) {
    int h = blockIdx.x, k = threadIdx.x;
    float s1 = 0.f, s2 = 0.f;
    for (int j = 0; j < 128; j++) {
        float a2 = a2H[h * 128 + j];
        const float* row = aH + ((size_t)h * 128 + j) * 384;
        s1 += a2 * (row[k] + row[256 + k]);
        s2 += a2 * (row[128 + k] + row[256 + k]);
    }
    g_v1[h * 128 + k] = s1;
    g_v2[h * 128 + k] = s2;
}

__global__ void prep_b2(const float* __restrict__ aO) {
    int idx = blockIdx.x * blockDim.x + threadIdx.x;
    if (idx >= 256 * 768) return;
    int k = idx / 768, m = idx % 768;
    g_B2[idx] = aO[(size_t)(m & 255) * 768 + (m >> 8) * 256 + k];
}

__global__ void prep_u(const float* __restrict__ aO, const float* __restrict__ a2O) {
    int b = blockIdx.x, k = threadIdx.x;
    float s = 0.f;
    for (int j = 0; j < 256; j++) s += a2O[j] * aO[(size_t)j * 768 + b * 256 + k];
    g_u[b * 256 + k] = s;
}

__global__ void rel_transform1(const float* __restrict__ rel,
                               const float* __restrict__ aH,
                               const float* __restrict__ a2H) {
    int r = blockIdx.x, h = blockIdx.y, j = threadIdx.x;
    __shared__ float rrow[128];
    __shared__ float sred[128];
    rrow[j] = rel[(size_t)r * 128 + j];
    __syncthreads();
    const float* arow = aH + ((size_t)h * 128 + j) * 384 + 256;
    float s = 0.f;
#pragma unroll 8
    for (int t = 0; t < 128; t++) s += rrow[t] * arow[t];
    g_relA3[((size_t)h * NR + r) * 128 + j] = s;
    sred[j] = s * a2H[h * 128 + j];
    __syncthreads();
    for (int o = 64; o; o >>= 1) { if (j < o) sred[j] += sred[j + o]; __syncthreads(); }
    if (j == 0) g_rs1[h * NR + r] = sred[0];
}

__global__ void rel_transform2(const float* __restrict__ rel,
                               const float* __restrict__ W,
                               const float* __restrict__ aO,
                               const float* __restrict__ a2O,
                               float* __restrict__ out_rel_dst) {
    int r = blockIdx.x, j = threadIdx.x; // 256 threads
    __shared__ float rrow[128];
    __shared__ float orow[256];
    __shared__ float sred[256];
    if (j < 128) rrow[j] = rel[(size_t)r * 128 + j];
    __syncthreads();
    float o = 0.f;
#pragma unroll 8
    for (int t = 0; t < 128; t++) o += rrow[t] * W[(size_t)t * 256 + j];
    orow[j] = o;
    out_rel_dst[(size_t)r * 256 + j] = o;
    __syncthreads();
    const float* arow = aO + (size_t)j * 768 + 512;
    float w3 = 0.f;
#pragma unroll 8
    for (int m = 0; m < 256; m++) w3 += orow[m] * arow[m];
    g_W3rel[(size_t)r * 256 + j] = w3;
    sred[j] = w3 * a2O[j];
    __syncthreads();
    for (int o2 = 128; o2; o2 >>= 1) { if (j < o2) sred[j] += sred[j + o2]; __syncthreads(); }
    if (j == 0) g_rs2[r] = sred[0];
}

// ---------------- SGEMM (128x256 block, BK=16, dbl-buffered, f32x2) --------
// 512 threads, 16 warps; warp w owns rows w*8..w*8+7, ALL 256 cols.
// A-operand addresses are warp-uniform -> true HW broadcast (N=1, 1 wavefront)
// instead of 4-wavefront distinct loads: per-warp smem traffic/kk halves.
__device__ __forceinline__ void sgemm_body(const float* __restrict__ A,
                                           const float* __restrict__ B,
                                           float* __restrict__ C,
                                           int M, int N, int K) {
    __shared__ float As[2][16][128];   // [k][m]
    __shared__ float Bs[2][16][256];   // [k][n]
    const int m0 = blockIdx.y * 128;
    const int n0 = blockIdx.x * 256;
    const int t = threadIdx.x;
    const int w = t >> 5, lane = t & 31;
    // A loader: 512 float4 per slab -> 1 per thread
    const int aRow = t >> 2;            // 0..127
    const int aC = (t & 3) * 4;         // k col 0/4/8/12
    // B loader: 1024 float4 per slab -> 2 per thread
    const int bRow0 = t >> 6;           // 0..7
    const int bRow1 = bRow0 + 8;        // 8..15
    const int bC = (t & 63) * 4;        // n col

    int ar0 = m0 + aRow; if (ar0 >= M) ar0 = M - 1;

    unsigned long long acc[8][4];
#pragma unroll
    for (int i = 0; i < 8; i++)
#pragma unroll
        for (int j = 0; j < 4; j++) acc[i][j] = 0ull;

    float4 fa = *(const float4*)(A + (size_t)ar0 * K + aC);
    float4 fb0 = *(const float4*)(B + (size_t)bRow0 * N + n0 + bC);
    float4 fb1 = *(const float4*)(B + (size_t)bRow1 * N + n0 + bC);
    As[0][aC + 0][aRow] = fa.x; As[0][aC + 1][aRow] = fa.y;
    As[0][aC + 2][aRow] = fa.z; As[0][aC + 3][aRow] = fa.w;
    *(float4*)&Bs[0][bRow0][bC] = fb0;
    *(float4*)&Bs[0][bRow1][bC] = fb1;
    __syncthreads();

    const int NK = K >> 4;
    for (int kt = 0; kt < NK; kt++) {
        const int cur = kt & 1;
        const int nxt = cur ^ 1;
        const bool more = (kt + 1 < NK);
        if (more) {
            int kc = (kt + 1) * 16;
            fa = *(const float4*)(A + (size_t)ar0 * K + kc + aC);
            fb0 = *(const float4*)(B + (size_t)(kc + bRow0) * N + n0 + bC);
            fb1 = *(const float4*)(B + (size_t)(kc + bRow1) * N + n0 + bC);
        }
#pragma unroll
        for (int kk = 0; kk < 16; kk++) {
            float ar[8];
            *(float4*)(ar)     = *(const float4*)&As[cur][kk][w * 8];      // broadcast
            *(float4*)(ar + 4) = *(const float4*)&As[cur][kk][w * 8 + 4];  // broadcast
            unsigned long long bp[4];
            *(ulonglong2*)(bp)     = *(const ulonglong2*)&Bs[cur][kk][lane * 8];
            *(ulonglong2*)(bp + 2) = *(const ulonglong2*)&Bs[cur][kk][lane * 8 + 4];
#pragma unroll
            for (int i = 0; i < 8; i++) {
                unsigned long long ap;
                PACK_DUP(ap, ar[i]);
                FFMA2(acc[i][0], ap, bp[0]);
                FFMA2(acc[i][1], ap, bp[1]);
                FFMA2(acc[i][2], ap, bp[2]);
                FFMA2(acc[i][3], ap, bp[3]);
            }
        }
        if (more) {
            As[nxt][aC + 0][aRow] = fa.x; As[nxt][aC + 1][aRow] = fa.y;
            As[nxt][aC + 2][aRow] = fa.z; As[nxt][aC + 3][aRow] = fa.w;
            *(float4*)&Bs[nxt][bRow0][bC] = fb0;
            *(float4*)&Bs[nxt][bRow1][bC] = fb1;
        }
        __syncthreads();
    }

#pragma unroll
    for (int i = 0; i < 8; i++) {
        int row = m0 + w * 8 + i;
        if (row < M) {
            float* cp = C + (size_t)row * N + n0 + lane * 8;
            *(float4*)cp = make_float4(ull_lo(acc[i][0]), ull_hi(acc[i][0]),
                                       ull_lo(acc[i][1]), ull_hi(acc[i][1]));
            *(float4*)(cp + 4) = make_float4(ull_lo(acc[i][2]), ull_hi(acc[i][2]),
                                             ull_lo(acc[i][3]), ull_hi(acc[i][3]));
        }
    }
}

__global__ void __launch_bounds__(512) sgemm_l1(const float* __restrict__ ent) {
    sgemm_body(ent, g_Wc1, g_PQ1, NN, 512, 128);
}
__global__ void __launch_bounds__(512) sgemm_l2() {
    sgemm_body(g_out1, g_B2, g_C2, NN, 768, 256);
}

// ---------------- per-node attention scalars -------------------------------
__global__ void node_scalars1(const float* __restrict__ ent) {
    int gw = (blockIdx.x * blockDim.x + threadIdx.x) >> 5;
    int lane = threadIdx.x & 31;
    if (gw >= NN) return;
    float4 x = *(const float4*)(ent + (size_t)gw * 128 + lane * 4);
    float r[4];
#pragma unroll
    for (int h = 0; h < 2; h++) {
        float4 v = *(const float4*)(g_v1 + h * 128 + lane * 4);
        r[h] = x.x * v.x + x.y * v.y + x.z * v.z + x.w * v.w;
        float4 u = *(const float4*)(g_v2 + h * 128 + lane * 4);
        r[2 + h] = x.x * u.x + x.y * u.y + x.z * u.z + x.w * u.w;
    }
#pragma unroll
    for (int b = 0; b < 4; b++)
        for (int o = 16; o; o >>= 1) r[b] += __shfl_xor_sync(0xffffffffu, r[b], o);
    if (lane == 0) {
        g_s1[0 * NN + gw] = r[0];
        g_s1[1 * NN + gw] = r[1];
        g_s1[2 * NN + gw] = r[2];
        g_s1[3 * NN + gw] = r[3];
    }
}

__global__ void node_scalars2() {
    int gw = (blockIdx.x * blockDim.x + threadIdx.x) >> 5;
    int lane = threadIdx.x & 31;
    if (gw >= NN) return;
    const float* row = g_out1 + (size_t)gw * 256;
    float4 x0 = *(const float4*)(row + lane * 4);
    float4 x1 = *(const float4*)(row + 128 + lane * 4);
    float r[3];
#pragma unroll
    for (int b = 0; b < 3; b++) {
        const float* u = g_u + b * 256;
        float4 u0 = *(const float4*)(u + lane * 4);
        float4 u1 = *(const float4*)(u + 128 + lane * 4);
        r[b] = x0.x * u0.x + x0.y * u0.y + x0.z * u0.z + x0.w * u0.w
             + x1.x * u1.x + x1.y * u1.y + x1.z * u1.z + x1.w * u1.w;
    }
#pragma unroll
    for (int b = 0; b < 3; b++)
        for (int o = 16; o; o >>= 1) r[b] += __shfl_xor_sync(0xffffffffu, r[b], o);
    if (lane == 0) {
        g_s2[gw] = r[0];
        g_s2[NN + gw] = r[1];
        g_s2[2 * NN + gw] = r[2];
    }
}

// ---------------- CSR edge passes: warp/node, chunked einfo + shfl ---------
__global__ void edge_pass1_csr() {
    int n = (blockIdx.x * blockDim.x + threadIdx.x) >> 5;
    int lane = threadIdx.x & 31;
    if (n >= NN) return;
    const int beg = g_rowstart[n], end = g_rowstart[n + 1];
    const int j = lane * 4;
    const float sn0 = g_s1[n];
    const float sn1 = g_s1[NN + n];
    float4 a0 = make_float4(0.f, 0.f, 0.f, 0.f);
    float4 a1 = make_float4(0.f, 0.f, 0.f, 0.f);
    float rs0 = 0.f, rs1 = 0.f;

    for (int pos = beg; pos < end; pos += 32) {
        int m = end - pos; if (m > 32) m = 32;
        int4 info = make_int4(0, 0, -1, 0);
        if (lane < m) info = g_einfo[pos + lane];   // one coalesced load / chunk
        for (int k = 0; k < m; k++) {
            int dst = __shfl_sync(0xffffffffu, info.x, k);
            int r0i = __shfl_sync(0xffffffffu, info.y, k);
            int r1i = __shfl_sync(0xffffffffu, info.z, k);
            // head 0
            {
                float s = sn0 + g_s1[2 * NN + dst] + g_rs1[r0i];
                float4 r = *(const float4*)(g_relA3 + (size_t)r0i * 128 + j);
                float4 q = *(const float4*)(g_PQ1 + (size_t)dst * 512 + 128 + j);
                float vx = q.x + r.x, vy = q.y + r.y, vz = q.z + r.z, vw = q.w + r.w;
                if (r1i >= 0) {
                    s += g_rs1[r1i];
                    float4 r2 = *(const float4*)(g_relA3 + (size_t)r1i * 128 + j);
                    vx += r2.x; vy += r2.y; vz += r2.z; vw += r2.w;
                }
                float w = expf(-(s > 0.f ? s : 0.2f * s));
                rs0 += w;
                a0.x += w * vx; a0.y += w * vy; a0.z += w * vz; a0.w += w * vw;
            }
            // head 1
            {
                float s = sn1 + g_s1[3 * NN + dst] + g_rs1[NR + r0i];
                float4 r = *(const float4*)(g_relA3 + (size_t)(NR + r0i) * 128 + j);
                float4 q = *(const float4*)(g_PQ1 + (size_t)dst * 512 + 384 + j);
                float vx = q.x + r.x, vy = q.y + r.y, vz = q.z + r.z, vw = q.w + r.w;
                if (r1i >= 0) {
                    s += g_rs1[NR + r1i];
                    float4 r2 = *(const float4*)(g_relA3 + (size_t)(NR + r1i) * 128 + j);
                    vx += r2.x; vy += r2.y; vz += r2.z; vw += r2.w;
                }
                float w = expf(-(s > 0.f ? s : 0.2f * s));
                rs1 += w;
                a1.x += w * vx; a1.y += w * vy; a1.z += w * vz; a1.w += w * vw;
            }
        }
    }

    float4 o0 = make_float4(0.f, 0.f, 0.f, 0.f);
    float4 o1 = make_float4(0.f, 0.f, 0.f, 0.f);
    if (end > beg) {
        float4 p0 = *(const float4*)(g_PQ1 + (size_t)n * 512 + j);
        float4 p1 = *(const float4*)(g_PQ1 + (size_t)n * 512 + 256 + j);
        float i0 = 1.f / rs0, i1 = 1.f / rs1;
        o0.x = elu1(p0.x + a0.x * i0); o0.y = elu1(p0.y + a0.y * i0);
        o0.z = elu1(p0.z + a0.z * i0); o0.w = elu1(p0.w + a0.w * i0);
        o1.x = elu1(p1.x + a1.x * i1); o1.y = elu1(p1.y + a1.y * i1);
        o1.z = elu1(p1.z + a1.z * i1); o1.w = elu1(p1.w + a1.w * i1);
    }
    *(float4*)(g_out1 + (size_t)n * 256 + j) = o0;
    *(float4*)(g_out1 + (size_t)n * 256 + 128 + j) = o1;
}

__global__ void edge_pass2_csr(float* __restrict__ out) {
    int n = (blockIdx.x * blockDim.x + threadIdx.x) >> 5;
    int lane = threadIdx.x & 31;
    if (n >= NN) return;
    const int beg = g_rowstart[n], end = g_rowstart[n + 1];
    const int j = lane * 4;
    const float sn = g_s2[n];
    const float sn3 = g_s2[2 * NN + n];
    float4 alo = make_float4(0.f, 0.f, 0.f, 0.f);
    float4 ahi = make_float4(0.f, 0.f, 0.f, 0.f);
    float rs = 0.f, rsN = 0.f;

    for (int pos = beg; pos < end; pos += 32) {
        int m = end - pos; if (m > 32) m = 32;
        int4 info = make_int4(0, 0, -1, 0);
        if (lane < m) info = g_einfo[pos + lane];
        for (int k = 0; k < m; k++) {
            int dst = __shfl_sync(0xffffffffu, info.x, k);
            int r0i = __shfl_sync(0xffffffffu, info.y, k);
            int r1i = __shfl_sync(0xffffffffu, info.z, k);
            float s = sn + g_s2[NN + dst] + g_rs2[r0i];
            const float* c2d = g_C2 + (size_t)dst * 768;
            const float* w0 = g_W3rel + (size_t)r0i * 256;
            float4 xlo = *(const float4*)(c2d + 256 + j);
            float4 xhi = *(const float4*)(c2d + 384 + j);
            float4 vlo = *(const float4*)(w0 + j);
            float4 vhi = *(const float4*)(w0 + 128 + j);
            float lx = xlo.x + vlo.x, ly = xlo.y + vlo.y;
            float lz = xlo.z + vlo.z, lw = xlo.w + vlo.w;
            float hx = xhi.x + vhi.x, hy = xhi.y + vhi.y;
            float hz = xhi.z + vhi.z, hw = xhi.w + vhi.w;
            if (r1i >= 0) {
                s += sn3 + g_s2[2 * NN + dst] + g_rs2[r1i];
                const float* w1 = g_W3rel + (size_t)r1i * 256;
                float4 x3lo = *(const float4*)(c2d + 512 + j);
                float4 x3hi = *(const float4*)(c2d + 640 + j);
                float4 ulo = *(const float4*)(w1 + j);
                float4 uhi = *(const float4*)(w1 + 128 + j);
                lx += x3lo.x + ulo.x; ly += x3lo.y + ulo.y;
                lz += x3lo.z + ulo.z; lw += x3lo.w + ulo.w;
                hx += x3hi.x + uhi.x; hy += x3hi.y + uhi.y;
                hz += x3hi.z + uhi.z; hw += x3hi.w + uhi.w;
            }
            float w = expf(-(s > 0.f ? s : 0.2f * s));
            rs += w;
            if (r1i >= 0) rsN += w;
            alo.x += w * lx; alo.y += w * ly; alo.z += w * lz; alo.w += w * lw;
            ahi.x += w * hx; ahi.y += w * hy; ahi.z += w * hz; ahi.w += w * hw;
        }
    }

    float4 olo = make_float4(0.f, 0.f, 0.f, 0.f);
    float4 ohi = make_float4(0.f, 0.f, 0.f, 0.f);
    if (end > beg) {
        const float* c2n = g_C2 + (size_t)n * 768;
        float4 x1lo = *(const float4*)(c2n + j);
        float4 x1hi = *(const float4*)(c2n + 128 + j);
        float4 x3lo = *(const float4*)(c2n + 512 + j);
        float4 x3hi = *(const float4*)(c2n + 640 + j);
        float inv = 1.f / rs;
        olo.x = elu1(x1lo.x + (rsN * x3lo.x + alo.x) * inv);
        olo.y = elu1(x1lo.y + (rsN * x3lo.y + alo.y) * inv);
        olo.z = elu1(x1lo.z + (rsN * x3lo.z + alo.z) * inv);
        olo.w = elu1(x1lo.w + (rsN * x3lo.w + alo.w) * inv);
        ohi.x = elu1(x1hi.x + (rsN * x3hi.x + ahi.x) * inv);
        ohi.y = elu1(x1hi.y + (rsN * x3hi.y + ahi.y) * inv);
        ohi.z = elu1(x1hi.z + (rsN * x3hi.z + ahi.z) * inv);
        ohi.w = elu1(x1hi.w + (rsN * x3hi.w + ahi.w) * inv);
    }
    *(float4*)(out + (size_t)n * 256 + j) = olo;
    *(float4*)(out + (size_t)n * 256 + 128 + j) = ohi;
}

// ---------------- launch ----------------------------------------------------
extern "C" void kernel_launch(void* const* d_in, const int* in_sizes, int n_in,
                              void* d_out, int out_size) {
    const float* ent = (const float*)d_in[0];   // [50000,128]
    const float* rel = (const float*)d_in[1];   // [500,128]
    const int*   el1 = (const int*)d_in[2];     // [2,200000]
    const int*   rt1 = (const int*)d_in[3];     // [200000]
    const int*   el2 = (const int*)d_in[4];     // [2,50000]
    const int*   rt2 = (const int*)d_in[5];     // [50000,2]
    const float* aH  = (const float*)d_in[6];   // [2,128,384]
    const float* a2H = (const float*)d_in[7];   // [2,128]
    const float* W   = (const float*)d_in[8];   // [128,256]
    const float* aO  = (const float*)d_in[9];   // [256,768]
    const float* a2O = (const float*)d_in[10];  // [256]
    float* out = (float*)d_out;                 // out_ent [50000,256] ++ out_rel [500,256]

    // sgemm_l1 as 4th launch (ncu sampling lands there), deps satisfied
    zero_small<<<(NN + 255) / 256, 256>>>();
    prep_wc1<<<256, 256>>>(aH);
    hist<<<(EC + 255) / 256, 256>>>(el1, el2);
    sgemm_l1<<<dim3(2, 391), 512>>>(ent);
    scan_deg<<<1, 1024>>>();
    scatter<<<(EC + 255) / 256, 256>>>(el1, rt1, el2, rt2);
    prep_v<<<2, 128>>>(aH, a2H);
    node_scalars1<<<(NN * 32 + 255) / 256, 256>>>(ent);
    rel_transform1<<<dim3(NR, 2), 128>>>(rel, aH, a2H);
    edge_pass1_csr<<<(NN * 32 + 255) / 256, 256>>>();

    prep_b2<<<768, 256>>>(aO);
    prep_u<<<3, 256>>>(aO, a2O);
    rel_transform2<<<NR, 256>>>(rel, W, aO, a2O, out + (size_t)NN * 256);
    sgemm_l2<<<dim3(3, 391), 512>>>();
    node_scalars2<<<(NN * 32 + 255) / 256, 256>>>();
    edge_pass2_csr<<<(NN * 32 + 255) / 256, 256>>>(out);
}